// round 11
// baseline (speedup 1.0000x reference)
#include <cuda_runtime.h>

// SE block, one persistent kernel, 152 blocks (1/SM) x 1024 threads.
// Phase 1 = TMA (cp.async.bulk) 4-deep smem pipeline, pure-read at bulk-engine
//           bandwidth (LDG read path measured to cap at ~4.2 TB/s; TMA hit 4.7+).
// Phase 2 = per-batch arrival counters (replay-safe mod-256) + tiny MLP.
// Phase 3 = R9's direct reverse streaming: __ldcs reads (L2-warm: TMA filled
//           L2 in phase 1), __stcs writes.

#define C        256
#define BOT      32
#define HW       3136
#define HW4      784
#define PLANE_BYTES (HW * 4)
#define BC       8192
#define GRID     152
#define NTHREADS 1024
#define NBUF     4
#define PLB      2
#define BUF_F4   (PLB * HW4)            // 1568 float4 per buffer
#define P1_ITERS 27                     // ceil(54/2)

struct __align__(128) Smem {
    float4 buf[NBUF][BUF_F4];           // 100352 B
    unsigned long long mbar[NBUF];
    float pb[2][2][32];                 // [iter&1][plane_in_buf][warp]
    float s[2][C];
    float h[2][BOT];
    float g[64];
};

__device__ float d_s[BC];
__device__ unsigned int d_cnt[32];      // per-batch counters (never reset)

__device__ __forceinline__ unsigned smem_u32(const void* p) {
    return (unsigned)__cvta_generic_to_shared(p);
}
__device__ __forceinline__ void mbar_init(unsigned a, unsigned cnt) {
    asm volatile("mbarrier.init.shared.b64 [%0], %1;" :: "r"(a), "r"(cnt) : "memory");
}
__device__ __forceinline__ void mbar_expect_tx(unsigned a, unsigned bytes) {
    asm volatile("mbarrier.arrive.expect_tx.shared.b64 _, [%0], %1;"
                 :: "r"(a), "r"(bytes) : "memory");
}
__device__ __forceinline__ void bulk_ld(unsigned dst, const void* src,
                                        unsigned bytes, unsigned bar) {
    asm volatile(
        "cp.async.bulk.shared::cluster.global.mbarrier::complete_tx::bytes "
        "[%0], [%1], %2, [%3];"
        :: "r"(dst), "l"(src), "r"(bytes), "r"(bar) : "memory");
}
__device__ __forceinline__ void mbar_wait(unsigned a, unsigned parity) {
    asm volatile(
        "{\n\t.reg .pred P;\n"
        "W%=:\n\t"
        "mbarrier.try_wait.parity.shared.b64 P, [%0], %1;\n\t"
        "@P bra D%=;\n\t"
        "bra W%=;\n"
        "D%=:\n\t}"
        :: "r"(a), "r"(parity) : "memory");
}

__device__ __forceinline__ void issue_load(Smem* sm, const float* __restrict__ x,
                                           int p0, int nk, int iter) {
    const int base = iter * PLB;
    if (base >= nk) return;
    int planes = nk - base; if (planes > PLB) planes = PLB;
    const unsigned bytes = (unsigned)planes * PLANE_BYTES;
    const int slot = iter & (NBUF - 1);
    const unsigned bar = smem_u32(&sm->mbar[slot]);
    const unsigned dst = smem_u32(&sm->buf[slot][0]);
    mbar_expect_tx(bar, bytes);
    bulk_ld(dst, x + (size_t)(p0 + base) * HW, bytes, bar);
}

__global__ void __launch_bounds__(NTHREADS, 1) se_fused_kernel(
    const float* __restrict__ x,
    const float* __restrict__ w1, const float* __restrict__ b1,
    const float* __restrict__ w2, const float* __restrict__ b2,
    float* __restrict__ out)
{
    extern __shared__ unsigned char smem_raw[];
    Smem* sm = reinterpret_cast<Smem*>(smem_raw);

    const int tid  = threadIdx.x;
    const int warp = tid >> 5;
    const int lane = tid & 31;
    const int bid  = blockIdx.x;

    const int p0 = (int)(((long long)bid * BC) / GRID);
    const int p1 = (int)(((long long)(bid + 1) * BC) / GRID);
    const int nk = p1 - p0;                    // 53 or 54 planes
    const int b0 = p0 >> 8;
    const int nb = ((p1 - 1) >> 8) - b0 + 1;   // 1 or 2 batches
    const int n0 = min((b0 + 1) * C, p1) - p0;
    const int n1 = nk - n0;
    const int iters = (nk + PLB - 1) / PLB;    // 27

    if (tid == 0) {
        #pragma unroll
        for (int i = 0; i < NBUF; i++) mbar_init(smem_u32(&sm->mbar[i]), 1);
    }
    __syncthreads();
    if (tid == 0) {
        #pragma unroll
        for (int i = 0; i < NBUF; i++) issue_load(sm, x, p0, nk, i);
    }

    // ---------------- Phase 1: TMA pipeline reduce ---------------------------
    for (int it = 0; it < iters; ++it) {
        const int slot = it & (NBUF - 1);
        const unsigned parity = (unsigned)((it >> 2) & 1);
        const int base = it * PLB;
        int planes = nk - base; if (planes > PLB) planes = PLB;
        const int nf4 = planes * HW4;

        mbar_wait(smem_u32(&sm->mbar[slot]), parity);
        const float4* __restrict__ bp = sm->buf[slot];

        float accA = 0.f, accB = 0.f;
        {
            int i = tid;
            if (i < nf4) {
                float4 v = bp[i];
                float s = (v.x + v.y) + (v.z + v.w);
                if (i < HW4) accA += s; else accB += s;
            }
            i = tid + NTHREADS;
            if (i < nf4) {                 // >=1024 -> always plane 1
                float4 v = bp[i];
                accB += (v.x + v.y) + (v.z + v.w);
            }
        }
        #pragma unroll
        for (int o = 16; o > 0; o >>= 1) {
            accA += __shfl_xor_sync(0xffffffffu, accA, o);
            accB += __shfl_xor_sync(0xffffffffu, accB, o);
        }
        if (lane == 0) {
            sm->pb[it & 1][0][warp] = accA;
            sm->pb[it & 1][1][warp] = accB;
        }
        __syncthreads();                   // buffer fully consumed
        if (tid == 0) issue_load(sm, x, p0, nk, it + NBUF);
        if (warp < 2) {
            const int plane = base + warp;
            if (plane < nk) {
                float v = sm->pb[it & 1][warp][lane];
                #pragma unroll
                for (int o = 16; o > 0; o >>= 1)
                    v += __shfl_xor_sync(0xffffffffu, v, o);
                if (lane == 0)
                    d_s[p0 + plane] = v * (1.0f / (float)HW);
            }
        }
    }
    __threadfence();                        // publish d_s
    __syncthreads();

    // ------------- Per-batch arrive + wait (replay-safe, mod-256) -------------
    if (tid == 0) {
        atomicAdd(&d_cnt[b0], (unsigned)n0);
        if (n1 > 0) atomicAdd(&d_cnt[b0 + 1], (unsigned)n1);
        volatile unsigned int* vc = d_cnt;
        while (vc[b0] & 255u) __nanosleep(32);
        if (n1 > 0)
            while (vc[b0 + 1] & 255u) __nanosleep(32);
        __threadfence();
    }
    __syncthreads();

    // ---------------- Phase 2: means -> hidden -> gates -----------------------
    for (int idx = tid; idx < nb * C; idx += NTHREADS)
        sm->s[idx >> 8][idx & 255] = d_s[b0 * C + idx];
    __syncthreads();

    for (int j = warp; j < nb * BOT; j += 32) {
        const int bi = j >> 5, o = j & 31;
        const float* __restrict__ w1row = w1 + o * C;
        float acc = 0.0f;
        #pragma unroll
        for (int k = 0; k < 8; k++) {
            const int c = lane + 32 * k;
            acc = fmaf(sm->s[bi][c], __ldg(w1row + c), acc);
        }
        #pragma unroll
        for (int off = 16; off > 0; off >>= 1)
            acc += __shfl_xor_sync(0xffffffffu, acc, off);
        if (lane == 0) sm->h[bi][o] = fmaxf(acc + __ldg(b1 + o), 0.0f);
    }
    __syncthreads();

    if (tid < nk) {
        const int plane = p0 + tid;
        const int c = plane & 255;
        const int bi = (plane >> 8) - b0;
        const float* __restrict__ wrow = w2 + c * BOT;
        float acc = __ldg(b2 + c);
        #pragma unroll
        for (int o = 0; o < BOT; o++)
            acc = fmaf(sm->h[bi][o], __ldg(wrow + o), acc);
        sm->g[tid] = 1.0f / (1.0f + __expf(-acc));
    }
    __syncthreads();

    // ---------------- Phase 3: REVERSE direct streaming (R9) ------------------
    const unsigned int total = (unsigned int)nk * HW4;       // <= 42336
    const int nfull = (int)(total / (8u * NTHREADS));
    const float4* __restrict__ x4 =
        reinterpret_cast<const float4*>(x) + (size_t)p0 * HW4;
    float4* __restrict__ o4 = reinterpret_cast<float4*>(out) + (size_t)p0 * HW4;

    for (unsigned int i = (unsigned int)nfull * 8u * NTHREADS + tid; i < total;
         i += NTHREADS) {
        const float g = sm->g[i / HW4];
        float4 v = __ldcs(x4 + i);
        v.x *= g; v.y *= g; v.z *= g; v.w *= g;
        __stcs(o4 + i, v);
    }
    for (int it = nfull - 1; it >= 0; --it) {
        const unsigned int i = (unsigned int)it * 8u * NTHREADS + tid;
        float4 v0 = __ldcs(x4 + i);
        float4 v1 = __ldcs(x4 + i + 1 * NTHREADS);
        float4 v2 = __ldcs(x4 + i + 2 * NTHREADS);
        float4 v3 = __ldcs(x4 + i + 3 * NTHREADS);
        float4 v4 = __ldcs(x4 + i + 4 * NTHREADS);
        float4 v5 = __ldcs(x4 + i + 5 * NTHREADS);
        float4 v6 = __ldcs(x4 + i + 6 * NTHREADS);
        float4 v7 = __ldcs(x4 + i + 7 * NTHREADS);
        const float g0 = sm->g[(i) / HW4];
        const float g1 = sm->g[(i + 1 * NTHREADS) / HW4];
        const float g2 = sm->g[(i + 2 * NTHREADS) / HW4];
        const float g3 = sm->g[(i + 3 * NTHREADS) / HW4];
        const float g4 = sm->g[(i + 4 * NTHREADS) / HW4];
        const float g5 = sm->g[(i + 5 * NTHREADS) / HW4];
        const float g6 = sm->g[(i + 6 * NTHREADS) / HW4];
        const float g7 = sm->g[(i + 7 * NTHREADS) / HW4];
        v0.x *= g0; v0.y *= g0; v0.z *= g0; v0.w *= g0;
        v1.x *= g1; v1.y *= g1; v1.z *= g1; v1.w *= g1;
        v2.x *= g2; v2.y *= g2; v2.z *= g2; v2.w *= g2;
        v3.x *= g3; v3.y *= g3; v3.z *= g3; v3.w *= g3;
        v4.x *= g4; v4.y *= g4; v4.z *= g4; v4.w *= g4;
        v5.x *= g5; v5.y *= g5; v5.z *= g5; v5.w *= g5;
        v6.x *= g6; v6.y *= g6; v6.z *= g6; v6.w *= g6;
        v7.x *= g7; v7.y *= g7; v7.z *= g7; v7.w *= g7;
        __stcs(o4 + i,                v0);
        __stcs(o4 + i + 1 * NTHREADS, v1);
        __stcs(o4 + i + 2 * NTHREADS, v2);
        __stcs(o4 + i + 3 * NTHREADS, v3);
        __stcs(o4 + i + 4 * NTHREADS, v4);
        __stcs(o4 + i + 5 * NTHREADS, v5);
        __stcs(o4 + i + 6 * NTHREADS, v6);
        __stcs(o4 + i + 7 * NTHREADS, v7);
    }
}

extern "C" void kernel_launch(void* const* d_in, const int* in_sizes, int n_in,
                              void* d_out, int out_size) {
    const float* x  = (const float*)d_in[0];
    const float* w1 = (const float*)d_in[1];
    const float* b1 = (const float*)d_in[2];
    const float* w2 = (const float*)d_in[3];
    const float* b2 = (const float*)d_in[4];
    float* out = (float*)d_out;

    static bool attr_set = false;
    if (!attr_set) {
        cudaFuncSetAttribute(se_fused_kernel,
                             cudaFuncAttributeMaxDynamicSharedMemorySize,
                             (int)sizeof(Smem));
        attr_set = true;
    }
    se_fused_kernel<<<GRID, NTHREADS, sizeof(Smem)>>>(x, w1, b1, w2, b2, out);
}